// round 12
// baseline (speedup 1.0000x reference)
#include <cuda_runtime.h>
#include <cuda_bf16.h>

// Problem constants (fixed by the reference)
#define BG   128              // graphs
#define NN_  512              // nodes per graph
#define FF   128              // feature dim
#define DEG  16
#define ETOT (BG*NN_*DEG)     // 1,048,576 edges
#define NTOT (BG*NN_)         // 65,536 nodes
#define ADJ_WORDS (BG*NN_*(NN_/32))  // 4MB bitmask
#define PADN 64               // padded neighbor-list stride (multiple of 4)

// -------- device-global scratch (no allocations allowed) --------
__device__ unsigned int   g_adj[ADJ_WORDS];
__device__ unsigned int   g_nbr32[(size_t)NTOT * PADN + 4];  // byte offsets node*72 (+pad for prefetch)
__device__ float          g_dinv[NTOT];
__device__ unsigned int   g_pc[NTOT];                   // degree-sorted: node | cnt4<<16
__device__ float g_acc[(size_t)NTOT * FF];   // 32MB
__device__ float g_y[(size_t)NTOT * FF];     // 32MB
__device__ float g_pool[512 * 128];          // per-(graph-quarter) col sums
__device__ unsigned int g_wt1[16384];        // W1^T split: hi pairs / lo pairs
__device__ unsigned int g_wt2[16384];        // W2^T split

// ---------------- adjacency build ----------------
__global__ void build_adj_kernel(const int* __restrict__ ei) {
    int e = blockIdx.x * blockDim.x + threadIdx.x;
    if (e >= ETOT) return;
    int src = ei[e];
    int dst = ei[ETOT + e];
    int g  = src >> 9;         // N = 512
    int si = src & 511;
    int di = dst & 511;
    atomicOr(&g_adj[(g * 512 + si) * 16 + (di >> 5)], 1u << (di & 31));
}

// Fused: expand bitmask -> u32 byte-offset lists (node*72 = padded bf16 u-row offset),
// dinv, then per-graph counting sort by degree -> g_pc. One block per graph.
__global__ void __launch_bounds__(512) expand_sort_kernel() {
    __shared__ unsigned hist[17];
    __shared__ unsigned basep[17];
    int g = blockIdx.x, tid = threadIdx.x;
    int i = g * 512 + tid;

    int cnt = 0;
    unsigned* row = &g_nbr32[(size_t)i * PADN];
#pragma unroll
    for (int w = 0; w < 16; w++) {
        unsigned int bits = g_adj[i * 16 + w];
        while (bits) {
            int b = __ffs(bits) - 1;
            bits &= bits - 1;
            if (cnt < PADN) row[cnt] = (unsigned)((w * 32 + b) * 72);  // node*72
            cnt++;
        }
    }
    if (cnt > PADN) cnt = PADN;
    g_dinv[i] = (cnt > 0) ? rsqrtf((float)cnt) : 0.0f;
    int cnt4 = (cnt + 3) & ~3;
    for (int e = cnt; e < cnt4; e++) row[e] = 512u * 72u;   // zero row at node 512

    if (tid < 17) hist[tid] = 0;
    __syncthreads();
    int bin = cnt4 >> 2;   // 0..16
    atomicAdd(&hist[bin], 1);
    __syncthreads();
    if (tid == 0) {
        unsigned s = 0;
        for (int k = 0; k < 17; k++) { basep[k] = s; s += hist[k]; }
    }
    __syncthreads();
    unsigned pos = atomicAdd(&basep[bin], 1);
    g_pc[g * 512 + pos] = (unsigned)tid | ((unsigned)cnt4 << 16);
}

// Transpose + hi/lo bf16 split of both weights in one launch.
__global__ void prep_w_kernel(const float* __restrict__ W1, const float* __restrict__ W2,
                              unsigned int* __restrict__ wt1, unsigned int* __restrict__ wt2) {
    int idx = blockIdx.x * blockDim.x + threadIdx.x;
    const float* W = (idx < 8192) ? W1 : W2;
    unsigned int* wt = (idx < 8192) ? wt1 : wt2;
    int id = idx & 8191;
    int n = id >> 6, k = (id & 63) * 2;
    float x0 = W[k * 128 + n];
    float x1 = W[(k + 1) * 128 + n];
    __nv_bfloat16 h0 = __float2bfloat16(x0);
    __nv_bfloat16 h1 = __float2bfloat16(x1);
    __nv_bfloat16 l0 = __float2bfloat16(x0 - __bfloat162float(h0));
    __nv_bfloat16 l1 = __float2bfloat16(x1 - __bfloat162float(h1));
    wt[id]        = (unsigned int)__bfloat16_as_ushort(h0) | ((unsigned int)__bfloat16_as_ushort(h1) << 16);
    wt[8192 + id] = (unsigned int)__bfloat16_as_ushort(l0) | ((unsigned int)__bfloat16_as_ushort(l1) << 16);
}

// ---------------- bf16 helpers ----------------
__device__ __forceinline__ unsigned pack_bf16x2(float lo, float hi) {
    unsigned r;
    asm("cvt.rn.bf16x2.f32 %0, %1, %2;" : "=r"(r) : "f"(hi), "f"(lo));
    return r;
}
__device__ __forceinline__ float bf_lo(unsigned u) { return __uint_as_float(u << 16); }
__device__ __forceinline__ float bf_hi(unsigned u) { return __uint_as_float(u & 0xffff0000u); }

// ---------------- polynomial filter: acc = sum_{k=0..3} S^k x ----------------
// One CTA (1024 threads) per (graph, 32-col slice). Quarter-warp (8 lanes) per row;
// hop state u stored in BF16 with 72-byte row stride: 72*row mod 128 cycles through
// all 16 8B bank phases -> random-row gathers land conflict-free. fp32 accumulation.
#define FS 32
#define UROWS 513                        // row 512 = zero row
#define UROWB 72                         // padded bf16 row stride (bank-phase spreading)
#define POLY_U0   0
#define POLY_U1   (POLY_U0 + UROWS*UROWB)         // 36936
#define POLY_DINV (POLY_U1 + UROWS*UROWB)         // 73872
#define POLY_PC   (POLY_DINV + NN_*4)
#define POLY_SMEM (POLY_PC + NN_*4)               // 77968 B

__global__ void __launch_bounds__(1024, 1) poly_kernel(const float* __restrict__ xin) {
    extern __shared__ unsigned char smraw[];
    unsigned char* ubuf0 = smraw + POLY_U0;
    unsigned char* ubuf1 = smraw + POLY_U1;
    float* dinv_s  = (float*)(smraw + POLY_DINV);
    unsigned* pc_s = (unsigned*)(smraw + POLY_PC);

    int g  = blockIdx.y;
    int fb = blockIdx.x * FS;
    int tid = threadIdx.x, w = tid >> 5, lane = tid & 31;
    int q  = lane >> 3;            // quarter-warp id 0..3
    int li = lane & 7;             // lane in quarter; cols 4*li..4*li+3

    const char* nbr_base = (const char*)&g_nbr32[(size_t)g * 512 * PADN];

    if (tid < 512) {
        dinv_s[tid] = g_dinv[g * 512 + tid];
        pc_s[tid]   = g_pc[g * 512 + tid];
    }
    // zero row 512 (72B = 18 u32) of both u buffers
    if (tid >= 512 && tid < 530) *(unsigned*)(ubuf0 + 512 * UROWB + (tid - 512) * 4) = 0u;
    else if (tid >= 544 && tid < 562) *(unsigned*)(ubuf1 + 512 * UROWB + (tid - 544) * 4) = 0u;
    __syncthreads();

    // per-m row metadata in registers (fixed across hops)
    int rowm[4];
    int cntm[4];
    float dm[4];
    float acc[4][4];                   // fp32 accumulator, 4 cols per lane

    const char* xbase = (const char*)(xin + (size_t)g * 512 * FF + fb) + li * 16;
#pragma unroll
    for (int m = 0; m < 4; m++) {
        int pos = m * 128 + ((m & 1) ? (124 - 4 * w) : (4 * w)) + q;  // serpentine
        unsigned pc = pc_s[pos];
        int row = pc & 0xffffu;
        rowm[m] = row;
        cntm[m] = pc >> 16;
        float d = dinv_s[row];
        dm[m] = d;
        float4 xv = *(const float4*)(xbase + (size_t)row * 512);
        acc[m][0] = xv.x; acc[m][1] = xv.y; acc[m][2] = xv.z; acc[m][3] = xv.w;
        uint2 uw;
        uw.x = pack_bf16x2(d * xv.x, d * xv.y);
        uw.y = pack_bf16x2(d * xv.z, d * xv.w);
        *(uint2*)(ubuf0 + row * UROWB + li * 8) = uw;
    }
    __syncthreads();

    unsigned char* ucur = ubuf0;
    unsigned char* unew = ubuf1;
#pragma unroll 1
    for (int hop = 0; hop < 3; hop++) {
        const char* ucb = (const char*)ucur + li * 8;   // gather base (+row*72 offsets)
#pragma unroll
        for (int m = 0; m < 4; m++) {
            const uint4* rowp = (const uint4*)(nbr_base + ((size_t)rowm[m] << 8));
            int cnt4 = cntm[m];
            float s0 = 0.f, s1 = 0.f, s2 = 0.f, s3 = 0.f;
            uint4 pk = __ldg(rowp);
#pragma unroll 1
            for (int e = 0; e < cnt4; e += 4) {
                uint4 nx = __ldg(rowp + (e >> 2) + 1);   // prefetch (padded; safe)
                uint2 v0 = *(const uint2*)(ucb + pk.x);
                uint2 v1 = *(const uint2*)(ucb + pk.y);
                uint2 v2 = *(const uint2*)(ucb + pk.z);
                uint2 v3 = *(const uint2*)(ucb + pk.w);
                s0 += bf_lo(v0.x); s1 += bf_hi(v0.x); s2 += bf_lo(v0.y); s3 += bf_hi(v0.y);
                s0 += bf_lo(v1.x); s1 += bf_hi(v1.x); s2 += bf_lo(v1.y); s3 += bf_hi(v1.y);
                s0 += bf_lo(v2.x); s1 += bf_hi(v2.x); s2 += bf_lo(v2.y); s3 += bf_hi(v2.y);
                s0 += bf_lo(v3.x); s1 += bf_hi(v3.x); s2 += bf_lo(v3.y); s3 += bf_hi(v3.y);
                pk = nx;
            }
            float d = dm[m];
            float z0 = d * s0, z1 = d * s1, z2 = d * s2, z3 = d * s3;
            acc[m][0] += z0; acc[m][1] += z1; acc[m][2] += z2; acc[m][3] += z3;
            if (hop < 2) {
                uint2 uw;
                uw.x = pack_bf16x2(d * z0, d * z1);
                uw.y = pack_bf16x2(d * z2, d * z3);
                *(uint2*)(unew + rowm[m] * UROWB + li * 8) = uw;
            }
        }
        __syncthreads();
        unsigned char* t = ucur; ucur = unew; unew = t;
    }

    char* ybase = (char*)(g_acc + (size_t)g * 512 * FF + fb) + li * 16;
#pragma unroll
    for (int m = 0; m < 4; m++) {
        float4 ov;
        ov.x = acc[m][0]; ov.y = acc[m][1]; ov.z = acc[m][2]; ov.w = acc[m][3];
        *(float4*)(ybase + (size_t)rowm[m] * 512) = ov;
    }
}

// ---------------- mma.sync GEMM + bias + relu ----------------
// MODE 0: write Y. MODE 1: skip Y, emit per-CTA column sums of relu output
// (deterministic shfl-butterfly + smem partials) into pool[b*128 + c].
#define ASTR 136
#define GMM_AH 0
#define GMM_AL (GMM_AH + 128*ASTR*2)
#define GMM_BH (GMM_AL + 128*ASTR*2)
#define GMM_BL (GMM_BH + 128*ASTR*2)
#define GMM_BIAS (GMM_BL + 128*ASTR*2)
#define GMM_PART (GMM_BIAS + 128*4)
#define GEMM_MMA_SMEM (GMM_PART + 4*128*4)

__device__ __forceinline__ void mma16816(float* c, const unsigned* a, const unsigned* b) {
    asm volatile(
        "mma.sync.aligned.m16n8k16.row.col.f32.bf16.bf16.f32 "
        "{%0,%1,%2,%3}, {%4,%5,%6,%7}, {%8,%9}, {%0,%1,%2,%3};"
        : "+f"(c[0]), "+f"(c[1]), "+f"(c[2]), "+f"(c[3])
        : "r"(a[0]), "r"(a[1]), "r"(a[2]), "r"(a[3]), "r"(b[0]), "r"(b[1]));
}

template <int MODE>
__global__ void __launch_bounds__(256, 1) gemm_mma_kernel(
        const float* __restrict__ A, const unsigned int* __restrict__ wt,
        const float* __restrict__ bias, float* __restrict__ Y,
        float* __restrict__ pool) {
    extern __shared__ unsigned char smg[];
    unsigned short* Ah = (unsigned short*)(smg + GMM_AH);
    unsigned short* Al = (unsigned short*)(smg + GMM_AL);
    unsigned short* Bh = (unsigned short*)(smg + GMM_BH);
    unsigned short* Bl = (unsigned short*)(smg + GMM_BL);
    float* bias_s = (float*)(smg + GMM_BIAS);
    float* part   = (float*)(smg + GMM_PART);   // [4][128]

    int tid = threadIdx.x;
    int lane = tid & 31;
    int w = tid >> 5;
    int wr = w & 3;
    int wc = w >> 2;
    size_t rowbase = (size_t)blockIdx.x * 128;

    for (int idx = tid; idx < 8192; idx += 256) {
        int n = idx >> 6, p = idx & 63;
        *(unsigned int*)&Bh[n * ASTR + 2 * p] = wt[idx];
        *(unsigned int*)&Bl[n * ASTR + 2 * p] = wt[8192 + idx];
    }
    for (int idx = tid; idx < 8192; idx += 256) {
        int r = idx >> 6, p = idx & 63;
        float2 x = *(const float2*)(A + (rowbase + r) * 128 + 2 * p);
        __nv_bfloat16 h0 = __float2bfloat16(x.x);
        __nv_bfloat16 h1 = __float2bfloat16(x.y);
        __nv_bfloat16 l0 = __float2bfloat16(x.x - __bfloat162float(h0));
        __nv_bfloat16 l1 = __float2bfloat16(x.y - __bfloat162float(h1));
        *(unsigned int*)&Ah[r * ASTR + 2 * p] =
            (unsigned int)__bfloat16_as_ushort(h0) | ((unsigned int)__bfloat16_as_ushort(h1) << 16);
        *(unsigned int*)&Al[r * ASTR + 2 * p] =
            (unsigned int)__bfloat16_as_ushort(l0) | ((unsigned int)__bfloat16_as_ushort(l1) << 16);
    }
    if (tid < 128) bias_s[tid] = bias[tid];
    __syncthreads();

    float acc[2][8][4];
#pragma unroll
    for (int mt = 0; mt < 2; mt++)
#pragma unroll
        for (int nt = 0; nt < 8; nt++)
#pragma unroll
            for (int p = 0; p < 4; p++) acc[mt][nt][p] = 0.0f;

    int frow = lane >> 2;
    int fcolb = 2 * (lane & 3);

#pragma unroll
    for (int kk = 0; kk < 8; kk++) {
        int kc = fcolb + 16 * kk;
        unsigned ah[2][4], al[2][4], bh[8][2], bl[8][2];
#pragma unroll
        for (int mt = 0; mt < 2; mt++) {
            int r0 = 32 * wr + 16 * mt + frow;
            ah[mt][0] = *(const unsigned*)&Ah[r0 * ASTR + kc];
            ah[mt][1] = *(const unsigned*)&Ah[(r0 + 8) * ASTR + kc];
            ah[mt][2] = *(const unsigned*)&Ah[r0 * ASTR + kc + 8];
            ah[mt][3] = *(const unsigned*)&Ah[(r0 + 8) * ASTR + kc + 8];
            al[mt][0] = *(const unsigned*)&Al[r0 * ASTR + kc];
            al[mt][1] = *(const unsigned*)&Al[(r0 + 8) * ASTR + kc];
            al[mt][2] = *(const unsigned*)&Al[r0 * ASTR + kc + 8];
            al[mt][3] = *(const unsigned*)&Al[(r0 + 8) * ASTR + kc + 8];
        }
#pragma unroll
        for (int nt = 0; nt < 8; nt++) {
            int n0 = 64 * wc + 8 * nt + frow;
            bh[nt][0] = *(const unsigned*)&Bh[n0 * ASTR + kc];
            bh[nt][1] = *(const unsigned*)&Bh[n0 * ASTR + kc + 8];
            bl[nt][0] = *(const unsigned*)&Bl[n0 * ASTR + kc];
            bl[nt][1] = *(const unsigned*)&Bl[n0 * ASTR + kc + 8];
        }
#pragma unroll
        for (int mt = 0; mt < 2; mt++)
#pragma unroll
            for (int nt = 0; nt < 8; nt++) {
                mma16816(acc[mt][nt], ah[mt], bh[nt]);
                mma16816(acc[mt][nt], ah[mt], bl[nt]);
                mma16816(acc[mt][nt], al[mt], bh[nt]);
            }
    }

    if (MODE == 0) {
#pragma unroll
        for (int mt = 0; mt < 2; mt++) {
            size_t r0 = rowbase + 32 * wr + 16 * mt + frow;
#pragma unroll
            for (int nt = 0; nt < 8; nt++) {
                int col = 64 * wc + 8 * nt + fcolb;
                float b0 = bias_s[col], b1 = bias_s[col + 1];
                float2 v0, v1;
                float t;
                t = acc[0*mt+mt][nt][0] + b0; v0.x = t > 0 ? t : 0;
                t = acc[mt][nt][1] + b1; v0.y = t > 0 ? t : 0;
                t = acc[mt][nt][2] + b0; v1.x = t > 0 ? t : 0;
                t = acc[mt][nt][3] + b1; v1.y = t > 0 ? t : 0;
                *(float2*)(Y + r0 * 128 + col)       = v0;
                *(float2*)(Y + (r0 + 8) * 128 + col) = v1;
            }
        }
    } else {
        // column partial sums of relu output over this CTA's 128 rows
        float cs[8][2];
#pragma unroll
        for (int nt = 0; nt < 8; nt++) {
            int col = 64 * wc + 8 * nt + fcolb;
            float b0 = bias_s[col], b1 = bias_s[col + 1];
            float a0 = 0.f, a1 = 0.f;
#pragma unroll
            for (int mt = 0; mt < 2; mt++) {
                float t;
                t = acc[mt][nt][0] + b0; a0 += (t > 0 ? t : 0);
                t = acc[mt][nt][2] + b0; a0 += (t > 0 ? t : 0);
                t = acc[mt][nt][1] + b1; a1 += (t > 0 ? t : 0);
                t = acc[mt][nt][3] + b1; a1 += (t > 0 ? t : 0);
            }
            cs[nt][0] = a0; cs[nt][1] = a1;
        }
        // butterfly reduce over frow (lanes differing by multiples of 4)
#pragma unroll
        for (int nt = 0; nt < 8; nt++) {
#pragma unroll
            for (int sft = 4; sft < 32; sft <<= 1) {
                cs[nt][0] += __shfl_xor_sync(0xffffffffu, cs[nt][0], sft);
                cs[nt][1] += __shfl_xor_sync(0xffffffffu, cs[nt][1], sft);
            }
        }
        if (lane < 4) {
#pragma unroll
            for (int nt = 0; nt < 8; nt++) {
                part[wr * 128 + 64 * wc + 8 * nt + 2 * lane]     = cs[nt][0];
                part[wr * 128 + 64 * wc + 8 * nt + 2 * lane + 1] = cs[nt][1];
            }
        }
        __syncthreads();
        if (tid < 128) {
            pool[(size_t)blockIdx.x * 128 + tid] =
                part[tid] + part[128 + tid] + part[256 + tid] + part[384 + tid];
        }
    }
}

// ---------------- head: mean pool (from partials) -> MLP ----------------
__global__ void __launch_bounds__(128) head_kernel(
        const float* __restrict__ pool,
        const float* __restrict__ Wr1, const float* __restrict__ br1,
        const float* __restrict__ Wr2, const float* __restrict__ br2,
        float* __restrict__ out) {
    __shared__ float hs[128];
    __shared__ float rs[64];
    int g = blockIdx.x;
    int tid = threadIdx.x;

    {
        const float* p = pool + (size_t)(4 * g) * 128 + tid;
        hs[tid] = (p[0] + p[128] + p[256] + p[384]) * (1.0f / 512.0f);
    }
    __syncthreads();

    if (tid < 64) {
        float a = br1[tid];
        for (int k = 0; k < 128; k++) a += hs[k] * Wr1[k * 64 + tid];
        rs[tid] = a > 0 ? a : 0;
    }
    __syncthreads();

    if (tid == 0) {
        float a = br2[0];
        for (int o = 0; o < 64; o++) a += rs[o] * Wr2[o];
        out[g] = a;
    }
}

// ---------------- launch ----------------
extern "C" void kernel_launch(void* const* d_in, const int* in_sizes, int n_in,
                              void* d_out, int out_size) {
    const float* X   = (const float*)d_in[0];
    const int*   ei  = (const int*)d_in[2];
    const float* W1  = (const float*)d_in[3];
    const float* b1  = (const float*)d_in[4];
    const float* W2  = (const float*)d_in[5];
    const float* b2  = (const float*)d_in[6];
    const float* Wr1 = (const float*)d_in[7];
    const float* br1 = (const float*)d_in[8];
    const float* Wr2 = (const float*)d_in[9];
    const float* br2 = (const float*)d_in[10];
    float* out = (float*)d_out;

    cudaFuncSetAttribute(poly_kernel, cudaFuncAttributeMaxDynamicSharedMemorySize, POLY_SMEM);
    cudaFuncSetAttribute(gemm_mma_kernel<0>, cudaFuncAttributeMaxDynamicSharedMemorySize, GEMM_MMA_SMEM);
    cudaFuncSetAttribute(gemm_mma_kernel<1>, cudaFuncAttributeMaxDynamicSharedMemorySize, GEMM_MMA_SMEM);

    void* yaddr = nullptr;  cudaGetSymbolAddress(&yaddr, g_y);
    float* Yp = (float*)yaddr;
    void* aaddr = nullptr;  cudaGetSymbolAddress(&aaddr, g_acc);
    const float* Ap = (const float*)aaddr;
    void* w1addr = nullptr; cudaGetSymbolAddress(&w1addr, g_wt1);
    void* w2addr = nullptr; cudaGetSymbolAddress(&w2addr, g_wt2);
    void* adjaddr = nullptr; cudaGetSymbolAddress(&adjaddr, g_adj);
    void* pooladdr = nullptr; cudaGetSymbolAddress(&pooladdr, g_pool);
    float* Pp = (float*)pooladdr;

    // adjacency (rebuilt every call; deterministic)
    cudaMemsetAsync(adjaddr, 0, ADJ_WORDS * sizeof(unsigned int));
    build_adj_kernel<<<ETOT / 256, 256>>>(ei);
    expand_sort_kernel<<<BG, 512>>>();
    prep_w_kernel<<<64, 256>>>(W1, W2, (unsigned int*)w1addr, (unsigned int*)w2addr);

    dim3 pgrid(FF / FS, BG);

    // layer 1
    poly_kernel<<<pgrid, 1024, POLY_SMEM>>>(X);
    gemm_mma_kernel<0><<<NTOT / 128, 256, GEMM_MMA_SMEM>>>(Ap, (const unsigned int*)w1addr, b1, Yp, nullptr);
    // layer 2 (GEMM fuses the mean-pool partial sums; no Y write)
    poly_kernel<<<pgrid, 1024, POLY_SMEM>>>(Yp);
    gemm_mma_kernel<1><<<NTOT / 128, 256, GEMM_MMA_SMEM>>>(Ap, (const unsigned int*)w2addr, b2, nullptr, Pp);
    // head
    head_kernel<<<BG, 128>>>(Pp, Wr1, br1, Wr2, br2, out);
}

// round 13
// speedup vs baseline: 1.0731x; 1.0731x over previous
#include <cuda_runtime.h>
#include <cuda_bf16.h>

// Problem constants (fixed by the reference)
#define BG   128              // graphs
#define NN_  512              // nodes per graph
#define FF   128              // feature dim
#define DEG  16
#define ETOT (BG*NN_*DEG)     // 1,048,576 edges
#define NTOT (BG*NN_)         // 65,536 nodes
#define ADJ_WORDS (BG*NN_*(NN_/32))  // 4MB bitmask
#define PADN 64               // padded neighbor-list stride (multiple of 4)

// -------- device-global scratch (no allocations allowed) --------
__device__ unsigned int   g_adj[ADJ_WORDS];
__device__ unsigned int   g_nbr32[(size_t)NTOT * PADN + 4];  // byte offsets node*64 (+pad for prefetch)
__device__ float          g_dinv[NTOT];
__device__ unsigned int   g_pc[NTOT];                   // degree-sorted: node | cnt4<<16
__device__ float g_acc[(size_t)NTOT * FF];   // 32MB
__device__ float g_y[(size_t)NTOT * FF];     // 32MB
__device__ float g_pool[512 * 128];          // per-(graph-quarter) col sums
__device__ unsigned int g_wt1[16384];        // W1^T split: hi pairs / lo pairs
__device__ unsigned int g_wt2[16384];        // W2^T split

// ---------------- adjacency build ----------------
__global__ void build_adj_kernel(const int* __restrict__ ei) {
    int e = blockIdx.x * blockDim.x + threadIdx.x;
    if (e >= ETOT) return;
    int src = ei[e];
    int dst = ei[ETOT + e];
    int g  = src >> 9;         // N = 512
    int si = src & 511;
    int di = dst & 511;
    atomicOr(&g_adj[(g * 512 + si) * 16 + (di >> 5)], 1u << (di & 31));
}

// Fused: expand bitmask -> u32 byte-offset lists (node*64 = bf16 u-row offset),
// dinv, then per-graph counting sort by degree -> g_pc. One block per graph.
__global__ void __launch_bounds__(512) expand_sort_kernel() {
    __shared__ unsigned hist[17];
    __shared__ unsigned basep[17];
    int g = blockIdx.x, tid = threadIdx.x;
    int i = g * 512 + tid;

    int cnt = 0;
    unsigned* row = &g_nbr32[(size_t)i * PADN];
#pragma unroll
    for (int w = 0; w < 16; w++) {
        unsigned int bits = g_adj[i * 16 + w];
        while (bits) {
            int b = __ffs(bits) - 1;
            bits &= bits - 1;
            if (cnt < PADN) row[cnt] = (unsigned)((w * 32 + b) << 6);  // node*64
            cnt++;
        }
    }
    if (cnt > PADN) cnt = PADN;
    g_dinv[i] = (cnt > 0) ? rsqrtf((float)cnt) : 0.0f;
    int cnt4 = (cnt + 3) & ~3;
    for (int e = cnt; e < cnt4; e++) row[e] = 512u << 6;   // zero row at node 512

    if (tid < 17) hist[tid] = 0;
    __syncthreads();
    int bin = cnt4 >> 2;   // 0..16
    atomicAdd(&hist[bin], 1);
    __syncthreads();
    if (tid == 0) {
        unsigned s = 0;
        for (int k = 0; k < 17; k++) { basep[k] = s; s += hist[k]; }
    }
    __syncthreads();
    unsigned pos = atomicAdd(&basep[bin], 1);
    g_pc[g * 512 + pos] = (unsigned)tid | ((unsigned)cnt4 << 16);
}

// Transpose + hi/lo bf16 split of both weights in one launch.
__global__ void prep_w_kernel(const float* __restrict__ W1, const float* __restrict__ W2,
                              unsigned int* __restrict__ wt1, unsigned int* __restrict__ wt2) {
    int idx = blockIdx.x * blockDim.x + threadIdx.x;
    const float* W = (idx < 8192) ? W1 : W2;
    unsigned int* wt = (idx < 8192) ? wt1 : wt2;
    int id = idx & 8191;
    int n = id >> 6, k = (id & 63) * 2;
    float x0 = W[k * 128 + n];
    float x1 = W[(k + 1) * 128 + n];
    __nv_bfloat16 h0 = __float2bfloat16(x0);
    __nv_bfloat16 h1 = __float2bfloat16(x1);
    __nv_bfloat16 l0 = __float2bfloat16(x0 - __bfloat162float(h0));
    __nv_bfloat16 l1 = __float2bfloat16(x1 - __bfloat162float(h1));
    wt[id]        = (unsigned int)__bfloat16_as_ushort(h0) | ((unsigned int)__bfloat16_as_ushort(h1) << 16);
    wt[8192 + id] = (unsigned int)__bfloat16_as_ushort(l0) | ((unsigned int)__bfloat16_as_ushort(l1) << 16);
}

// ---------------- bf16 helpers ----------------
__device__ __forceinline__ unsigned pack_bf16x2(float lo, float hi) {
    unsigned r;
    asm("cvt.rn.bf16x2.f32 %0, %1, %2;" : "=r"(r) : "f"(hi), "f"(lo));
    return r;
}
__device__ __forceinline__ float bf_lo(unsigned u) { return __uint_as_float(u << 16); }
__device__ __forceinline__ float bf_hi(unsigned u) { return __uint_as_float(u & 0xffff0000u); }

// ---------------- polynomial filter: acc = sum_{k=0..3} S^k x ----------------
// One CTA (1024 threads) per (graph, 32-col slice). Quarter-warp (8 lanes) per row;
// hop state u stored in BF16 (64B aligned rows -> half the crossbar bytes of fp32).
// fp32 accumulation (exact unpack via shift); only u storage is rounded.
#define FS 32
#define UROWS 513                        // row 512 = zero row
#define UROWB 64                         // bf16 row bytes (64B-aligned: best measured)
#define POLY_U0   0
#define POLY_U1   (POLY_U0 + UROWS*UROWB)         // +32832
#define POLY_DINV (POLY_U1 + UROWS*UROWB)         // +32832
#define POLY_PC   (POLY_DINV + NN_*4)
#define POLY_SMEM (POLY_PC + NN_*4)               // ~69.7KB

__global__ void __launch_bounds__(1024, 1) poly_kernel(const float* __restrict__ xin) {
    extern __shared__ unsigned char smraw[];
    unsigned char* ubuf0 = smraw + POLY_U0;
    unsigned char* ubuf1 = smraw + POLY_U1;
    float* dinv_s  = (float*)(smraw + POLY_DINV);
    unsigned* pc_s = (unsigned*)(smraw + POLY_PC);

    int g  = blockIdx.y;
    int fb = blockIdx.x * FS;
    int tid = threadIdx.x, w = tid >> 5, lane = tid & 31;
    int q  = lane >> 3;            // quarter-warp id 0..3
    int li = lane & 7;             // lane in quarter; cols 4*li..4*li+3

    const char* nbr_base = (const char*)&g_nbr32[(size_t)g * 512 * PADN];

    if (tid < 512) {
        dinv_s[tid] = g_dinv[g * 512 + tid];
        pc_s[tid]   = g_pc[g * 512 + tid];
    }
    // zero row 512 (64B) of both u buffers
    if (tid >= 512 && tid < 528) *(unsigned*)(ubuf0 + 512 * UROWB + (tid - 512) * 4) = 0u;
    else if (tid >= 544 && tid < 560) *(unsigned*)(ubuf1 + 512 * UROWB + (tid - 544) * 4) = 0u;
    __syncthreads();

    // per-m row metadata in registers (fixed across hops)
    int roff[4];                       // row*64 : bf16 u-row byte offset
    int cntm[4];
    float dm[4];
    float acc[4][4];                   // fp32 accumulator, 4 cols per lane

    const char* xbase = (const char*)(xin + (size_t)g * 512 * FF + fb) + li * 16;
#pragma unroll
    for (int m = 0; m < 4; m++) {
        int pos = m * 128 + ((m & 1) ? (124 - 4 * w) : (4 * w)) + q;  // serpentine
        unsigned pc = pc_s[pos];
        int row = pc & 0xffffu;
        cntm[m] = pc >> 16;
        roff[m] = row << 6;
        float d = dinv_s[row];
        dm[m] = d;
        float4 xv = *(const float4*)(xbase + (size_t)roff[m] * 8);   // row*512 bytes
        acc[m][0] = xv.x; acc[m][1] = xv.y; acc[m][2] = xv.z; acc[m][3] = xv.w;
        uint2 uw;
        uw.x = pack_bf16x2(d * xv.x, d * xv.y);
        uw.y = pack_bf16x2(d * xv.z, d * xv.w);
        *(uint2*)(ubuf0 + roff[m] + li * 8) = uw;
    }
    __syncthreads();

    unsigned char* ucur = ubuf0;
    unsigned char* unew = ubuf1;
#pragma unroll 1
    for (int hop = 0; hop < 3; hop++) {
        const char* ucb = (const char*)ucur + li * 8;   // gather base (+row byte offset)
#pragma unroll
        for (int m = 0; m < 4; m++) {
            // nbr row byte offset = row*PADN*4 = roff*4
            const uint4* rowp = (const uint4*)(nbr_base + ((size_t)roff[m] << 2));
            int cnt4 = cntm[m];
            float s0 = 0.f, s1 = 0.f, s2 = 0.f, s3 = 0.f;
            uint4 pk = __ldg(rowp);
#pragma unroll 1
            for (int e = 0; e < cnt4; e += 4) {
                uint4 nx = __ldg(rowp + (e >> 2) + 1);   // prefetch (padded; safe)
                uint2 v0 = *(const uint2*)(ucb + pk.x);
                uint2 v1 = *(const uint2*)(ucb + pk.y);
                uint2 v2 = *(const uint2*)(ucb + pk.z);
                uint2 v3 = *(const uint2*)(ucb + pk.w);
                s0 += bf_lo(v0.x); s1 += bf_hi(v0.x); s2 += bf_lo(v0.y); s3 += bf_hi(v0.y);
                s0 += bf_lo(v1.x); s1 += bf_hi(v1.x); s2 += bf_lo(v1.y); s3 += bf_hi(v1.y);
                s0 += bf_lo(v2.x); s1 += bf_hi(v2.x); s2 += bf_lo(v2.y); s3 += bf_hi(v2.y);
                s0 += bf_lo(v3.x); s1 += bf_hi(v3.x); s2 += bf_lo(v3.y); s3 += bf_hi(v3.y);
                pk = nx;
            }
            float d = dm[m];
            float z0 = d * s0, z1 = d * s1, z2 = d * s2, z3 = d * s3;
            acc[m][0] += z0; acc[m][1] += z1; acc[m][2] += z2; acc[m][3] += z3;
            if (hop < 2) {
                uint2 uw;
                uw.x = pack_bf16x2(d * z0, d * z1);
                uw.y = pack_bf16x2(d * z2, d * z3);
                *(uint2*)(unew + roff[m] + li * 8) = uw;
            }
        }
        __syncthreads();
        unsigned char* t = ucur; ucur = unew; unew = t;
    }

    char* ybase = (char*)(g_acc + (size_t)g * 512 * FF + fb) + li * 16;
#pragma unroll
    for (int m = 0; m < 4; m++) {
        float4 ov;
        ov.x = acc[m][0]; ov.y = acc[m][1]; ov.z = acc[m][2]; ov.w = acc[m][3];
        *(float4*)(ybase + (size_t)roff[m] * 8) = ov;
    }
}

// ---------------- mma.sync GEMM + bias + relu ----------------
// MODE 0: write Y. MODE 1: skip Y, emit per-CTA column sums of relu output
// (deterministic shfl-butterfly + smem partials) into pool[b*128 + c].
#define ASTR 136
#define GMM_AH 0
#define GMM_AL (GMM_AH + 128*ASTR*2)
#define GMM_BH (GMM_AL + 128*ASTR*2)
#define GMM_BL (GMM_BH + 128*ASTR*2)
#define GMM_BIAS (GMM_BL + 128*ASTR*2)
#define GMM_PART (GMM_BIAS + 128*4)
#define GEMM_MMA_SMEM (GMM_PART + 4*128*4)

__device__ __forceinline__ void mma16816(float* c, const unsigned* a, const unsigned* b) {
    asm volatile(
        "mma.sync.aligned.m16n8k16.row.col.f32.bf16.bf16.f32 "
        "{%0,%1,%2,%3}, {%4,%5,%6,%7}, {%8,%9}, {%0,%1,%2,%3};"
        : "+f"(c[0]), "+f"(c[1]), "+f"(c[2]), "+f"(c[3])
        : "r"(a[0]), "r"(a[1]), "r"(a[2]), "r"(a[3]), "r"(b[0]), "r"(b[1]));
}

template <int MODE>
__global__ void __launch_bounds__(256, 1) gemm_mma_kernel(
        const float* __restrict__ A, const unsigned int* __restrict__ wt,
        const float* __restrict__ bias, float* __restrict__ Y,
        float* __restrict__ pool) {
    extern __shared__ unsigned char smg[];
    unsigned short* Ah = (unsigned short*)(smg + GMM_AH);
    unsigned short* Al = (unsigned short*)(smg + GMM_AL);
    unsigned short* Bh = (unsigned short*)(smg + GMM_BH);
    unsigned short* Bl = (unsigned short*)(smg + GMM_BL);
    float* bias_s = (float*)(smg + GMM_BIAS);
    float* part   = (float*)(smg + GMM_PART);   // [4][128]

    int tid = threadIdx.x;
    int lane = tid & 31;
    int w = tid >> 5;
    int wr = w & 3;
    int wc = w >> 2;
    size_t rowbase = (size_t)blockIdx.x * 128;

    for (int idx = tid; idx < 8192; idx += 256) {
        int n = idx >> 6, p = idx & 63;
        *(unsigned int*)&Bh[n * ASTR + 2 * p] = wt[idx];
        *(unsigned int*)&Bl[n * ASTR + 2 * p] = wt[8192 + idx];
    }
    for (int idx = tid; idx < 8192; idx += 256) {
        int r = idx >> 6, p = idx & 63;
        float2 x = *(const float2*)(A + (rowbase + r) * 128 + 2 * p);
        __nv_bfloat16 h0 = __float2bfloat16(x.x);
        __nv_bfloat16 h1 = __float2bfloat16(x.y);
        __nv_bfloat16 l0 = __float2bfloat16(x.x - __bfloat162float(h0));
        __nv_bfloat16 l1 = __float2bfloat16(x.y - __bfloat162float(h1));
        *(unsigned int*)&Ah[r * ASTR + 2 * p] =
            (unsigned int)__bfloat16_as_ushort(h0) | ((unsigned int)__bfloat16_as_ushort(h1) << 16);
        *(unsigned int*)&Al[r * ASTR + 2 * p] =
            (unsigned int)__bfloat16_as_ushort(l0) | ((unsigned int)__bfloat16_as_ushort(l1) << 16);
    }
    if (tid < 128) bias_s[tid] = bias[tid];
    __syncthreads();

    float acc[2][8][4];
#pragma unroll
    for (int mt = 0; mt < 2; mt++)
#pragma unroll
        for (int nt = 0; nt < 8; nt++)
#pragma unroll
            for (int p = 0; p < 4; p++) acc[mt][nt][p] = 0.0f;

    int frow = lane >> 2;
    int fcolb = 2 * (lane & 3);

#pragma unroll
    for (int kk = 0; kk < 8; kk++) {
        int kc = fcolb + 16 * kk;
        unsigned ah[2][4], al[2][4], bh[8][2], bl[8][2];
#pragma unroll
        for (int mt = 0; mt < 2; mt++) {
            int r0 = 32 * wr + 16 * mt + frow;
            ah[mt][0] = *(const unsigned*)&Ah[r0 * ASTR + kc];
            ah[mt][1] = *(const unsigned*)&Ah[(r0 + 8) * ASTR + kc];
            ah[mt][2] = *(const unsigned*)&Ah[r0 * ASTR + kc + 8];
            ah[mt][3] = *(const unsigned*)&Ah[(r0 + 8) * ASTR + kc + 8];
            al[mt][0] = *(const unsigned*)&Al[r0 * ASTR + kc];
            al[mt][1] = *(const unsigned*)&Al[(r0 + 8) * ASTR + kc];
            al[mt][2] = *(const unsigned*)&Al[r0 * ASTR + kc + 8];
            al[mt][3] = *(const unsigned*)&Al[(r0 + 8) * ASTR + kc + 8];
        }
#pragma unroll
        for (int nt = 0; nt < 8; nt++) {
            int n0 = 64 * wc + 8 * nt + frow;
            bh[nt][0] = *(const unsigned*)&Bh[n0 * ASTR + kc];
            bh[nt][1] = *(const unsigned*)&Bh[n0 * ASTR + kc + 8];
            bl[nt][0] = *(const unsigned*)&Bl[n0 * ASTR + kc];
            bl[nt][1] = *(const unsigned*)&Bl[n0 * ASTR + kc + 8];
        }
#pragma unroll
        for (int mt = 0; mt < 2; mt++)
#pragma unroll
            for (int nt = 0; nt < 8; nt++) {
                mma16816(acc[mt][nt], ah[mt], bh[nt]);
                mma16816(acc[mt][nt], ah[mt], bl[nt]);
                mma16816(acc[mt][nt], al[mt], bh[nt]);
            }
    }

    if (MODE == 0) {
#pragma unroll
        for (int mt = 0; mt < 2; mt++) {
            size_t r0 = rowbase + 32 * wr + 16 * mt + frow;
#pragma unroll
            for (int nt = 0; nt < 8; nt++) {
                int col = 64 * wc + 8 * nt + fcolb;
                float b0 = bias_s[col], b1 = bias_s[col + 1];
                float2 v0, v1;
                float t;
                t = acc[mt][nt][0] + b0; v0.x = t > 0 ? t : 0;
                t = acc[mt][nt][1] + b1; v0.y = t > 0 ? t : 0;
                t = acc[mt][nt][2] + b0; v1.x = t > 0 ? t : 0;
                t = acc[mt][nt][3] + b1; v1.y = t > 0 ? t : 0;
                *(float2*)(Y + r0 * 128 + col)       = v0;
                *(float2*)(Y + (r0 + 8) * 128 + col) = v1;
            }
        }
    } else {
        // column partial sums of relu output over this CTA's 128 rows
        float cs[8][2];
#pragma unroll
        for (int nt = 0; nt < 8; nt++) {
            int col = 64 * wc + 8 * nt + fcolb;
            float b0 = bias_s[col], b1 = bias_s[col + 1];
            float a0 = 0.f, a1 = 0.f;
#pragma unroll
            for (int mt = 0; mt < 2; mt++) {
                float t;
                t = acc[mt][nt][0] + b0; a0 += (t > 0 ? t : 0);
                t = acc[mt][nt][2] + b0; a0 += (t > 0 ? t : 0);
                t = acc[mt][nt][1] + b1; a1 += (t > 0 ? t : 0);
                t = acc[mt][nt][3] + b1; a1 += (t > 0 ? t : 0);
            }
            cs[nt][0] = a0; cs[nt][1] = a1;
        }
        // butterfly reduce over frow (lanes differing by multiples of 4)
#pragma unroll
        for (int nt = 0; nt < 8; nt++) {
#pragma unroll
            for (int sft = 4; sft < 32; sft <<= 1) {
                cs[nt][0] += __shfl_xor_sync(0xffffffffu, cs[nt][0], sft);
                cs[nt][1] += __shfl_xor_sync(0xffffffffu, cs[nt][1], sft);
            }
        }
        if (lane < 4) {
#pragma unroll
            for (int nt = 0; nt < 8; nt++) {
                part[wr * 128 + 64 * wc + 8 * nt + 2 * lane]     = cs[nt][0];
                part[wr * 128 + 64 * wc + 8 * nt + 2 * lane + 1] = cs[nt][1];
            }
        }
        __syncthreads();
        if (tid < 128) {
            pool[(size_t)blockIdx.x * 128 + tid] =
                part[tid] + part[128 + tid] + part[256 + tid] + part[384 + tid];
        }
    }
}

// ---------------- head: mean pool (from partials) -> MLP ----------------
__global__ void __launch_bounds__(128) head_kernel(
        const float* __restrict__ pool,
        const float* __restrict__ Wr1, const float* __restrict__ br1,
        const float* __restrict__ Wr2, const float* __restrict__ br2,
        float* __restrict__ out) {
    __shared__ float hs[128];
    __shared__ float rs[64];
    int g = blockIdx.x;
    int tid = threadIdx.x;

    {
        const float* p = pool + (size_t)(4 * g) * 128 + tid;
        hs[tid] = (p[0] + p[128] + p[256] + p[384]) * (1.0f / 512.0f);
    }
    __syncthreads();

    if (tid < 64) {
        float a = br1[tid];
        for (int k = 0; k < 128; k++) a += hs[k] * Wr1[k * 64 + tid];
        rs[tid] = a > 0 ? a : 0;
    }
    __syncthreads();

    if (tid == 0) {
        float a = br2[0];
        for (int o = 0; o < 64; o++) a += rs[o] * Wr2[o];
        out[g] = a;
    }
}

// ---------------- launch ----------------
extern "C" void kernel_launch(void* const* d_in, const int* in_sizes, int n_in,
                              void* d_out, int out_size) {
    const float* X   = (const float*)d_in[0];
    const int*   ei  = (const int*)d_in[2];
    const float* W1  = (const float*)d_in[3];
    const float* b1  = (const float*)d_in[4];
    const float* W2  = (const float*)d_in[5];
    const float* b2  = (const float*)d_in[6];
    const float* Wr1 = (const float*)d_in[7];
    const float* br1 = (const float*)d_in[8];
    const float* Wr2 = (const float*)d_in[9];
    const float* br2 = (const float*)d_in[10];
    float* out = (float*)d_out;

    cudaFuncSetAttribute(poly_kernel, cudaFuncAttributeMaxDynamicSharedMemorySize, POLY_SMEM);
    cudaFuncSetAttribute(gemm_mma_kernel<0>, cudaFuncAttributeMaxDynamicSharedMemorySize, GEMM_MMA_SMEM);
    cudaFuncSetAttribute(gemm_mma_kernel<1>, cudaFuncAttributeMaxDynamicSharedMemorySize, GEMM_MMA_SMEM);

    void* yaddr = nullptr;  cudaGetSymbolAddress(&yaddr, g_y);
    float* Yp = (float*)yaddr;
    void* aaddr = nullptr;  cudaGetSymbolAddress(&aaddr, g_acc);
    const float* Ap = (const float*)aaddr;
    void* w1addr = nullptr; cudaGetSymbolAddress(&w1addr, g_wt1);
    void* w2addr = nullptr; cudaGetSymbolAddress(&w2addr, g_wt2);
    void* adjaddr = nullptr; cudaGetSymbolAddress(&adjaddr, g_adj);
    void* pooladdr = nullptr; cudaGetSymbolAddress(&pooladdr, g_pool);
    float* Pp = (float*)pooladdr;

    // adjacency (rebuilt every call; deterministic)
    cudaMemsetAsync(adjaddr, 0, ADJ_WORDS * sizeof(unsigned int));
    build_adj_kernel<<<ETOT / 256, 256>>>(ei);
    expand_sort_kernel<<<BG, 512>>>();
    prep_w_kernel<<<64, 256>>>(W1, W2, (unsigned int*)w1addr, (unsigned int*)w2addr);

    dim3 pgrid(FF / FS, BG);

    // layer 1
    poly_kernel<<<pgrid, 1024, POLY_SMEM>>>(X);
    gemm_mma_kernel<0><<<NTOT / 128, 256, GEMM_MMA_SMEM>>>(Ap, (const unsigned int*)w1addr, b1, Yp, nullptr);
    // layer 2 (GEMM fuses the mean-pool partial sums; no Y write)
    poly_kernel<<<pgrid, 1024, POLY_SMEM>>>(Yp);
    gemm_mma_kernel<1><<<NTOT / 128, 256, GEMM_MMA_SMEM>>>(Ap, (const unsigned int*)w2addr, b2, nullptr, Pp);
    // head
    head_kernel<<<BG, 128>>>(Pp, Wr1, br1, Wr2, br2, out);
}

// round 14
// speedup vs baseline: 1.0751x; 1.0019x over previous
#include <cuda_runtime.h>
#include <cuda_bf16.h>

// Problem constants (fixed by the reference)
#define BG   128              // graphs
#define NN_  512              // nodes per graph
#define FF   128              // feature dim
#define DEG  16
#define ETOT (BG*NN_*DEG)     // 1,048,576 edges
#define NTOT (BG*NN_)         // 65,536 nodes
#define ADJ_WORDS (BG*NN_*(NN_/32))  // 4MB bitmask
#define PADN 64               // padded neighbor-list stride (multiple of 4)

// -------- device-global scratch (no allocations allowed) --------
__device__ unsigned int   g_adj[ADJ_WORDS];
__device__ unsigned int   g_nbr32[(size_t)NTOT * PADN + 4];  // byte offsets node*64 (+pad for prefetch)
__device__ float          g_dinv[NTOT];
__device__ unsigned int   g_pc[NTOT];                   // degree-sorted: node | cnt4<<16
__device__ float g_acc[(size_t)NTOT * FF];   // 32MB
__device__ float g_y[(size_t)NTOT * FF];     // 32MB
__device__ float g_pool[512 * 128];          // per-(graph-quarter) col sums
__device__ unsigned int g_wt1[16384];        // W1^T split: hi pairs / lo pairs
__device__ unsigned int g_wt2[16384];        // W2^T split

// ---------------- adjacency build ----------------
__global__ void build_adj_kernel(const int* __restrict__ ei) {
    int e = blockIdx.x * blockDim.x + threadIdx.x;
    if (e >= ETOT) return;
    int src = ei[e];
    int dst = ei[ETOT + e];
    int g  = src >> 9;         // N = 512
    int si = src & 511;
    int di = dst & 511;
    atomicOr(&g_adj[(g * 512 + si) * 16 + (di >> 5)], 1u << (di & 31));
}

// Fused: expand bitmask -> u32 byte-offset lists (node*64 = bf16 u-row offset),
// dinv, then per-graph counting sort by degree -> g_pc. One block per graph.
__global__ void __launch_bounds__(512) expand_sort_kernel() {
    __shared__ unsigned hist[17];
    __shared__ unsigned basep[17];
    int g = blockIdx.x, tid = threadIdx.x;
    int i = g * 512 + tid;

    int cnt = 0;
    unsigned* row = &g_nbr32[(size_t)i * PADN];
#pragma unroll
    for (int w = 0; w < 16; w++) {
        unsigned int bits = g_adj[i * 16 + w];
        while (bits) {
            int b = __ffs(bits) - 1;
            bits &= bits - 1;
            if (cnt < PADN) row[cnt] = (unsigned)((w * 32 + b) << 6);  // node*64
            cnt++;
        }
    }
    if (cnt > PADN) cnt = PADN;
    g_dinv[i] = (cnt > 0) ? rsqrtf((float)cnt) : 0.0f;
    int cnt4 = (cnt + 3) & ~3;
    for (int e = cnt; e < cnt4; e++) row[e] = 512u << 6;   // zero row at node 512

    if (tid < 17) hist[tid] = 0;
    __syncthreads();
    int bin = cnt4 >> 2;   // 0..16
    atomicAdd(&hist[bin], 1);
    __syncthreads();
    if (tid == 0) {
        unsigned s = 0;
        for (int k = 0; k < 17; k++) { basep[k] = s; s += hist[k]; }
    }
    __syncthreads();
    unsigned pos = atomicAdd(&basep[bin], 1);
    g_pc[g * 512 + pos] = (unsigned)tid | ((unsigned)cnt4 << 16);
}

// Transpose + hi/lo bf16 split of both weights in one launch.
__global__ void prep_w_kernel(const float* __restrict__ W1, const float* __restrict__ W2,
                              unsigned int* __restrict__ wt1, unsigned int* __restrict__ wt2) {
    int idx = blockIdx.x * blockDim.x + threadIdx.x;
    const float* W = (idx < 8192) ? W1 : W2;
    unsigned int* wt = (idx < 8192) ? wt1 : wt2;
    int id = idx & 8191;
    int n = id >> 6, k = (id & 63) * 2;
    float x0 = W[k * 128 + n];
    float x1 = W[(k + 1) * 128 + n];
    __nv_bfloat16 h0 = __float2bfloat16(x0);
    __nv_bfloat16 h1 = __float2bfloat16(x1);
    __nv_bfloat16 l0 = __float2bfloat16(x0 - __bfloat162float(h0));
    __nv_bfloat16 l1 = __float2bfloat16(x1 - __bfloat162float(h1));
    wt[id]        = (unsigned int)__bfloat16_as_ushort(h0) | ((unsigned int)__bfloat16_as_ushort(h1) << 16);
    wt[8192 + id] = (unsigned int)__bfloat16_as_ushort(l0) | ((unsigned int)__bfloat16_as_ushort(l1) << 16);
}

// ---------------- packed helpers ----------------
__device__ __forceinline__ void addx2(unsigned long long& a, unsigned long long b) {
    asm("add.rn.f32x2 %0, %0, %1;" : "+l"(a) : "l"(b));
}
__device__ __forceinline__ unsigned long long mulx2(unsigned long long a, unsigned long long b) {
    unsigned long long r;
    asm("mul.rn.f32x2 %0, %1, %2;" : "=l"(r) : "l"(a), "l"(b));
    return r;
}
__device__ __forceinline__ unsigned long long packx2(float lo, float hi) {
    unsigned long long r;
    asm("mov.b64 %0, {%1, %2};" : "=l"(r) : "f"(lo), "f"(hi));
    return r;
}
// bf16 pair (packed in u32) -> packed f32x2 (exact): lo = u<<16, hi = u & 0xffff0000
__device__ __forceinline__ unsigned long long bfpair(unsigned u) {
    unsigned long long r;
    asm("{\n\t.reg .b32 lo, hi;\n\t"
        "shl.b32 lo, %1, 16;\n\t"
        "and.b32 hi, %1, 0xffff0000;\n\t"
        "mov.b64 %0, {lo, hi};\n\t}"
        : "=l"(r) : "r"(u));
    return r;
}
// packed f32x2 -> bf16x2 (round-to-nearest)
__device__ __forceinline__ unsigned packbf_from_x2(unsigned long long p) {
    unsigned r;
    asm("{\n\t.reg .b32 lo, hi;\n\t"
        "mov.b64 {lo, hi}, %1;\n\t"
        "cvt.rn.bf16x2.f32 %0, hi, lo;\n\t}"
        : "=r"(r) : "l"(p));
    return r;
}
__device__ __forceinline__ void unpackx2(unsigned long long p, float& lo, float& hi) {
    asm("mov.b64 {%0, %1}, %2;" : "=f"(lo), "=f"(hi) : "l"(p));
}

// ---------------- polynomial filter: acc = sum_{k=0..3} S^k x ----------------
// One CTA (1024 threads) per (graph, 32-col slice). Quarter-warp (8 lanes) per row;
// hop state u stored in BF16 (64B aligned rows). fp32 math throughout via packed
// f32x2: unpack (SHF+LOP) feeds add.rn.f32x2 -> 3 issue slots per gathered u32.
#define FS 32
#define UROWS 513                        // row 512 = zero row
#define UROWB 64                         // bf16 row bytes
#define POLY_U0   0
#define POLY_U1   (POLY_U0 + UROWS*UROWB)         // +32832
#define POLY_DINV (POLY_U1 + UROWS*UROWB)         // +32832
#define POLY_PC   (POLY_DINV + NN_*4)
#define POLY_SMEM (POLY_PC + NN_*4)               // ~69.7KB

__global__ void __launch_bounds__(1024, 1) poly_kernel(const float* __restrict__ xin) {
    extern __shared__ unsigned char smraw[];
    unsigned char* ubuf0 = smraw + POLY_U0;
    unsigned char* ubuf1 = smraw + POLY_U1;
    float* dinv_s  = (float*)(smraw + POLY_DINV);
    unsigned* pc_s = (unsigned*)(smraw + POLY_PC);

    int g  = blockIdx.y;
    int fb = blockIdx.x * FS;
    int tid = threadIdx.x, w = tid >> 5, lane = tid & 31;
    int q  = lane >> 3;            // quarter-warp id 0..3
    int li = lane & 7;             // lane in quarter; cols 4*li..4*li+3

    const char* nbr_base = (const char*)&g_nbr32[(size_t)g * 512 * PADN];

    if (tid < 512) {
        dinv_s[tid] = g_dinv[g * 512 + tid];
        pc_s[tid]   = g_pc[g * 512 + tid];
    }
    // zero row 512 (64B) of both u buffers
    if (tid >= 512 && tid < 528) *(unsigned*)(ubuf0 + 512 * UROWB + (tid - 512) * 4) = 0u;
    else if (tid >= 544 && tid < 560) *(unsigned*)(ubuf1 + 512 * UROWB + (tid - 544) * 4) = 0u;
    __syncthreads();

    // per-m row metadata in registers (fixed across hops)
    int roff[4];                       // row*64 : bf16 u-row byte offset
    int cntm[4];
    unsigned long long ddm[4];         // packed (d, d)
    unsigned long long acc01[4], acc23[4];   // packed fp32 accumulators

    const char* xbase = (const char*)(xin + (size_t)g * 512 * FF + fb) + li * 16;
#pragma unroll
    for (int m = 0; m < 4; m++) {
        int pos = m * 128 + ((m & 1) ? (124 - 4 * w) : (4 * w)) + q;  // serpentine
        unsigned pc = pc_s[pos];
        int row = pc & 0xffffu;
        cntm[m] = pc >> 16;
        roff[m] = row << 6;
        float d = dinv_s[row];
        ddm[m] = packx2(d, d);
        float4 xv = *(const float4*)(xbase + (size_t)roff[m] * 8);   // row*512 bytes
        acc01[m] = packx2(xv.x, xv.y);
        acc23[m] = packx2(xv.z, xv.w);
        uint2 uw;
        uw.x = packbf_from_x2(mulx2(ddm[m], acc01[m]));
        uw.y = packbf_from_x2(mulx2(ddm[m], acc23[m]));
        *(uint2*)(ubuf0 + roff[m] + li * 8) = uw;
    }
    __syncthreads();

    unsigned char* ucur = ubuf0;
    unsigned char* unew = ubuf1;
#pragma unroll 1
    for (int hop = 0; hop < 3; hop++) {
        const char* ucb = (const char*)ucur + li * 8;   // gather base (+row byte offset)
#pragma unroll
        for (int m = 0; m < 4; m++) {
            // nbr row byte offset = row*PADN*4 = roff*4
            const uint4* rowp = (const uint4*)(nbr_base + ((size_t)roff[m] << 2));
            int cnt4 = cntm[m];
            unsigned long long s01 = 0ull, s23 = 0ull;
            uint4 pk = __ldg(rowp);
#pragma unroll 1
            for (int e = 0; e < cnt4; e += 4) {
                uint4 nx = __ldg(rowp + (e >> 2) + 1);   // prefetch (padded; safe)
                uint2 v0 = *(const uint2*)(ucb + pk.x);
                uint2 v1 = *(const uint2*)(ucb + pk.y);
                uint2 v2 = *(const uint2*)(ucb + pk.z);
                uint2 v3 = *(const uint2*)(ucb + pk.w);
                addx2(s01, bfpair(v0.x)); addx2(s23, bfpair(v0.y));
                addx2(s01, bfpair(v1.x)); addx2(s23, bfpair(v1.y));
                addx2(s01, bfpair(v2.x)); addx2(s23, bfpair(v2.y));
                addx2(s01, bfpair(v3.x)); addx2(s23, bfpair(v3.y));
                pk = nx;
            }
            unsigned long long z01 = mulx2(ddm[m], s01);
            unsigned long long z23 = mulx2(ddm[m], s23);
            addx2(acc01[m], z01); addx2(acc23[m], z23);
            if (hop < 2) {
                uint2 uw;
                uw.x = packbf_from_x2(mulx2(ddm[m], z01));
                uw.y = packbf_from_x2(mulx2(ddm[m], z23));
                *(uint2*)(unew + roff[m] + li * 8) = uw;
            }
        }
        __syncthreads();
        unsigned char* t = ucur; ucur = unew; unew = t;
    }

    char* ybase = (char*)(g_acc + (size_t)g * 512 * FF + fb) + li * 16;
#pragma unroll
    for (int m = 0; m < 4; m++) {
        float4 ov;
        unpackx2(acc01[m], ov.x, ov.y);
        unpackx2(acc23[m], ov.z, ov.w);
        *(float4*)(ybase + (size_t)roff[m] * 8) = ov;
    }
}

// ---------------- mma.sync GEMM + bias + relu ----------------
// MODE 0: write Y. MODE 1: skip Y, emit per-CTA column sums of relu output
// (deterministic shfl-butterfly + smem partials) into pool[b*128 + c].
#define ASTR 136
#define GMM_AH 0
#define GMM_AL (GMM_AH + 128*ASTR*2)
#define GMM_BH (GMM_AL + 128*ASTR*2)
#define GMM_BL (GMM_BH + 128*ASTR*2)
#define GMM_BIAS (GMM_BL + 128*ASTR*2)
#define GMM_PART (GMM_BIAS + 128*4)
#define GEMM_MMA_SMEM (GMM_PART + 4*128*4)

__device__ __forceinline__ void mma16816(float* c, const unsigned* a, const unsigned* b) {
    asm volatile(
        "mma.sync.aligned.m16n8k16.row.col.f32.bf16.bf16.f32 "
        "{%0,%1,%2,%3}, {%4,%5,%6,%7}, {%8,%9}, {%0,%1,%2,%3};"
        : "+f"(c[0]), "+f"(c[1]), "+f"(c[2]), "+f"(c[3])
        : "r"(a[0]), "r"(a[1]), "r"(a[2]), "r"(a[3]), "r"(b[0]), "r"(b[1]));
}

template <int MODE>
__global__ void __launch_bounds__(256, 1) gemm_mma_kernel(
        const float* __restrict__ A, const unsigned int* __restrict__ wt,
        const float* __restrict__ bias, float* __restrict__ Y,
        float* __restrict__ pool) {
    extern __shared__ unsigned char smg[];
    unsigned short* Ah = (unsigned short*)(smg + GMM_AH);
    unsigned short* Al = (unsigned short*)(smg + GMM_AL);
    unsigned short* Bh = (unsigned short*)(smg + GMM_BH);
    unsigned short* Bl = (unsigned short*)(smg + GMM_BL);
    float* bias_s = (float*)(smg + GMM_BIAS);
    float* part   = (float*)(smg + GMM_PART);   // [4][128]

    int tid = threadIdx.x;
    int lane = tid & 31;
    int w = tid >> 5;
    int wr = w & 3;
    int wc = w >> 2;
    size_t rowbase = (size_t)blockIdx.x * 128;

    for (int idx = tid; idx < 8192; idx += 256) {
        int n = idx >> 6, p = idx & 63;
        *(unsigned int*)&Bh[n * ASTR + 2 * p] = wt[idx];
        *(unsigned int*)&Bl[n * ASTR + 2 * p] = wt[8192 + idx];
    }
    for (int idx = tid; idx < 8192; idx += 256) {
        int r = idx >> 6, p = idx & 63;
        float2 x = *(const float2*)(A + (rowbase + r) * 128 + 2 * p);
        __nv_bfloat16 h0 = __float2bfloat16(x.x);
        __nv_bfloat16 h1 = __float2bfloat16(x.y);
        __nv_bfloat16 l0 = __float2bfloat16(x.x - __bfloat162float(h0));
        __nv_bfloat16 l1 = __float2bfloat16(x.y - __bfloat162float(h1));
        *(unsigned int*)&Ah[r * ASTR + 2 * p] =
            (unsigned int)__bfloat16_as_ushort(h0) | ((unsigned int)__bfloat16_as_ushort(h1) << 16);
        *(unsigned int*)&Al[r * ASTR + 2 * p] =
            (unsigned int)__bfloat16_as_ushort(l0) | ((unsigned int)__bfloat16_as_ushort(l1) << 16);
    }
    if (tid < 128) bias_s[tid] = bias[tid];
    __syncthreads();

    float acc[2][8][4];
#pragma unroll
    for (int mt = 0; mt < 2; mt++)
#pragma unroll
        for (int nt = 0; nt < 8; nt++)
#pragma unroll
            for (int p = 0; p < 4; p++) acc[mt][nt][p] = 0.0f;

    int frow = lane >> 2;
    int fcolb = 2 * (lane & 3);

#pragma unroll
    for (int kk = 0; kk < 8; kk++) {
        int kc = fcolb + 16 * kk;
        unsigned ah[2][4], al[2][4], bh[8][2], bl[8][2];
#pragma unroll
        for (int mt = 0; mt < 2; mt++) {
            int r0 = 32 * wr + 16 * mt + frow;
            ah[mt][0] = *(const unsigned*)&Ah[r0 * ASTR + kc];
            ah[mt][1] = *(const unsigned*)&Ah[(r0 + 8) * ASTR + kc];
            ah[mt][2] = *(const unsigned*)&Ah[r0 * ASTR + kc + 8];
            ah[mt][3] = *(const unsigned*)&Ah[(r0 + 8) * ASTR + kc + 8];
            al[mt][0] = *(const unsigned*)&Al[r0 * ASTR + kc];
            al[mt][1] = *(const unsigned*)&Al[(r0 + 8) * ASTR + kc];
            al[mt][2] = *(const unsigned*)&Al[r0 * ASTR + kc + 8];
            al[mt][3] = *(const unsigned*)&Al[(r0 + 8) * ASTR + kc + 8];
        }
#pragma unroll
        for (int nt = 0; nt < 8; nt++) {
            int n0 = 64 * wc + 8 * nt + frow;
            bh[nt][0] = *(const unsigned*)&Bh[n0 * ASTR + kc];
            bh[nt][1] = *(const unsigned*)&Bh[n0 * ASTR + kc + 8];
            bl[nt][0] = *(const unsigned*)&Bl[n0 * ASTR + kc];
            bl[nt][1] = *(const unsigned*)&Bl[n0 * ASTR + kc + 8];
        }
#pragma unroll
        for (int mt = 0; mt < 2; mt++)
#pragma unroll
            for (int nt = 0; nt < 8; nt++) {
                mma16816(acc[mt][nt], ah[mt], bh[nt]);
                mma16816(acc[mt][nt], ah[mt], bl[nt]);
                mma16816(acc[mt][nt], al[mt], bh[nt]);
            }
    }

    if (MODE == 0) {
#pragma unroll
        for (int mt = 0; mt < 2; mt++) {
            size_t r0 = rowbase + 32 * wr + 16 * mt + frow;
#pragma unroll
            for (int nt = 0; nt < 8; nt++) {
                int col = 64 * wc + 8 * nt + fcolb;
                float b0 = bias_s[col], b1 = bias_s[col + 1];
                float2 v0, v1;
                float t;
                t = acc[mt][nt][0] + b0; v0.x = t > 0 ? t : 0;
                t = acc[mt][nt][1] + b1; v0.y = t > 0 ? t : 0;
                t = acc[mt][nt][2] + b0; v1.x = t > 0 ? t : 0;
                t = acc[mt][nt][3] + b1; v1.y = t > 0 ? t : 0;
                *(float2*)(Y + r0 * 128 + col)       = v0;
                *(float2*)(Y + (r0 + 8) * 128 + col) = v1;
            }
        }
    } else {
        // column partial sums of relu output over this CTA's 128 rows
        float cs[8][2];
#pragma unroll
        for (int nt = 0; nt < 8; nt++) {
            int col = 64 * wc + 8 * nt + fcolb;
            float b0 = bias_s[col], b1 = bias_s[col + 1];
            float a0 = 0.f, a1 = 0.f;
#pragma unroll
            for (int mt = 0; mt < 2; mt++) {
                float t;
                t = acc[mt][nt][0] + b0; a0 += (t > 0 ? t : 0);
                t = acc[mt][nt][2] + b0; a0 += (t > 0 ? t : 0);
                t = acc[mt][nt][1] + b1; a1 += (t > 0 ? t : 0);
                t = acc[mt][nt][3] + b1; a1 += (t > 0 ? t : 0);
            }
            cs[nt][0] = a0; cs[nt][1] = a1;
        }
        // butterfly reduce over frow (lanes differing by multiples of 4)
#pragma unroll
        for (int nt = 0; nt < 8; nt++) {
#pragma unroll
            for (int sft = 4; sft < 32; sft <<= 1) {
                cs[nt][0] += __shfl_xor_sync(0xffffffffu, cs[nt][0], sft);
                cs[nt][1] += __shfl_xor_sync(0xffffffffu, cs[nt][1], sft);
            }
        }
        if (lane < 4) {
#pragma unroll
            for (int nt = 0; nt < 8; nt++) {
                part[wr * 128 + 64 * wc + 8 * nt + 2 * lane]     = cs[nt][0];
                part[wr * 128 + 64 * wc + 8 * nt + 2 * lane + 1] = cs[nt][1];
            }
        }
        __syncthreads();
        if (tid < 128) {
            pool[(size_t)blockIdx.x * 128 + tid] =
                part[tid] + part[128 + tid] + part[256 + tid] + part[384 + tid];
        }
    }
}

// ---------------- head: mean pool (from partials) -> MLP ----------------
__global__ void __launch_bounds__(128) head_kernel(
        const float* __restrict__ pool,
        const float* __restrict__ Wr1, const float* __restrict__ br1,
        const float* __restrict__ Wr2, const float* __restrict__ br2,
        float* __restrict__ out) {
    __shared__ float hs[128];
    __shared__ float rs[64];
    int g = blockIdx.x;
    int tid = threadIdx.x;

    {
        const float* p = pool + (size_t)(4 * g) * 128 + tid;
        hs[tid] = (p[0] + p[128] + p[256] + p[384]) * (1.0f / 512.0f);
    }
    __syncthreads();

    if (tid < 64) {
        float a = br1[tid];
        for (int k = 0; k < 128; k++) a += hs[k] * Wr1[k * 64 + tid];
        rs[tid] = a > 0 ? a : 0;
    }
    __syncthreads();

    if (tid == 0) {
        float a = br2[0];
        for (int o = 0; o < 64; o++) a += rs[o] * Wr2[o];
        out[g] = a;
    }
}

// ---------------- launch ----------------
extern "C" void kernel_launch(void* const* d_in, const int* in_sizes, int n_in,
                              void* d_out, int out_size) {
    const float* X   = (const float*)d_in[0];
    const int*   ei  = (const int*)d_in[2];
    const float* W1  = (const float*)d_in[3];
    const float* b1  = (const float*)d_in[4];
    const float* W2  = (const float*)d_in[5];
    const float* b2  = (const float*)d_in[6];
    const float* Wr1 = (const float*)d_in[7];
    const float* br1 = (const float*)d_in[8];
    const float* Wr2 = (const float*)d_in[9];
    const float* br2 = (const float*)d_in[10];
    float* out = (float*)d_out;

    cudaFuncSetAttribute(poly_kernel, cudaFuncAttributeMaxDynamicSharedMemorySize, POLY_SMEM);
    cudaFuncSetAttribute(gemm_mma_kernel<0>, cudaFuncAttributeMaxDynamicSharedMemorySize, GEMM_MMA_SMEM);
    cudaFuncSetAttribute(gemm_mma_kernel<1>, cudaFuncAttributeMaxDynamicSharedMemorySize, GEMM_MMA_SMEM);

    void* yaddr = nullptr;  cudaGetSymbolAddress(&yaddr, g_y);
    float* Yp = (float*)yaddr;
    void* aaddr = nullptr;  cudaGetSymbolAddress(&aaddr, g_acc);
    const float* Ap = (const float*)aaddr;
    void* w1addr = nullptr; cudaGetSymbolAddress(&w1addr, g_wt1);
    void* w2addr = nullptr; cudaGetSymbolAddress(&w2addr, g_wt2);
    void* adjaddr = nullptr; cudaGetSymbolAddress(&adjaddr, g_adj);
    void* pooladdr = nullptr; cudaGetSymbolAddress(&pooladdr, g_pool);
    float* Pp = (float*)pooladdr;

    // adjacency (rebuilt every call; deterministic)
    cudaMemsetAsync(adjaddr, 0, ADJ_WORDS * sizeof(unsigned int));
    build_adj_kernel<<<ETOT / 256, 256>>>(ei);
    expand_sort_kernel<<<BG, 512>>>();
    prep_w_kernel<<<64, 256>>>(W1, W2, (unsigned int*)w1addr, (unsigned int*)w2addr);

    dim3 pgrid(FF / FS, BG);

    // layer 1
    poly_kernel<<<pgrid, 1024, POLY_SMEM>>>(X);
    gemm_mma_kernel<0><<<NTOT / 128, 256, GEMM_MMA_SMEM>>>(Ap, (const unsigned int*)w1addr, b1, Yp, nullptr);
    // layer 2 (GEMM fuses the mean-pool partial sums; no Y write)
    poly_kernel<<<pgrid, 1024, POLY_SMEM>>>(Yp);
    gemm_mma_kernel<1><<<NTOT / 128, 256, GEMM_MMA_SMEM>>>(Ap, (const unsigned int*)w2addr, b2, nullptr, Pp);
    // head
    head_kernel<<<BG, 128>>>(Pp, Wr1, br1, Wr2, br2, out);
}